// round 15
// baseline (speedup 1.0000x reference)
#include <cuda_runtime.h>
#include <cuda_bf16.h>

// Problem constants (fixed by setup_inputs)
#define HEIGHT 256
#define WIDTH  256
#define NBATCH 128
#define NK     4
#define NPAR   28
#define PIX    (HEIGHT * WIDTH)
#define PPT    16                      // pixels per thread (8 packed pairs)
#define THREADS 256
#define PPB    (THREADS * PPT)         // 4096 pixels per block

typedef unsigned long long u64;

// ---- packed f32x2 helpers (sm_103a FFMA2 path, PTX-only) ----
__device__ __forceinline__ u64 pk2(float lo, float hi) {
    u64 r; asm("mov.b64 %0, {%1, %2};" : "=l"(r) : "f"(lo), "f"(hi)); return r;
}
__device__ __forceinline__ void upk2(u64 v, float& lo, float& hi) {
    asm("mov.b64 {%0, %1}, %2;" : "=f"(lo), "=f"(hi) : "l"(v));
}
__device__ __forceinline__ u64 fma2(u64 a, u64 b, u64 c) {
    u64 d; asm("fma.rn.f32x2 %0, %1, %2, %3;" : "=l"(d) : "l"(a), "l"(b), "l"(c)); return d;
}
__device__ __forceinline__ u64 mul2(u64 a, u64 b) {
    u64 d; asm("mul.rn.f32x2 %0, %1, %2;" : "=l"(d) : "l"(a), "l"(b)); return d;
}
__device__ __forceinline__ u64 add2(u64 a, u64 b) {
    u64 d; asm("add.rn.f32x2 %0, %1, %2;" : "=l"(d) : "l"(a), "l"(b)); return d;
}
__device__ __forceinline__ float fast_ex2(float x) {
    float r; asm("ex2.approx.f32 %0, %1;" : "=f"(r) : "f"(x)); return r;
}

__global__ __launch_bounds__(THREADS, 4)
void moe_gauss_kernel(const float* __restrict__ params, float* __restrict__ out) {
    const int b   = blockIdx.y;
    const int p0  = blockIdx.x * PPB + threadIdx.x * PPT;
    const int row = p0 >> 8;           // all 16 pixels share the same row (16 | 256)
    const int j0  = p0 & 255;

    const float* __restrict__ p = params + b * NPAR;

    const float dl = 1.0f / 255.0f;    // grid step
    const float x  = (float)row * dl;
    const float h  = 0.7213475204444817f;   // 0.5 * log2(e)

    const float yA_lo = (float)j0 * dl;          // group A: pairs 0..3 (pixels 0..7)
    const float yA_hi = (float)(j0 + 1) * dl;
    const float yB_lo = (float)(j0 + 8) * dl;    // group B: pairs 4..7 (pixels 8..15)
    const float yB_hi = (float)(j0 + 9) * dl;

    // Exponent f(y) = al*y^2 + be*y + ga (the -0.5*log2e factor folded in).
    // Geometric recurrence over pairs (stride 2*dl), restarted in two groups:
    //   e <- e*r,  r <- r*q ;  r(y)=ex2(4*al*dl*y + 4*al*dl^2 + 2*be*dl),
    //   q = ex2(8*al*dl^2) constant.
    // Two parallel 4-step chains per Gaussian (A, B) => 16 independent mul
    // chains + 2 accumulator trees, vs R11's 16-step serial chains.
    u64 EA[NK], RA[NK], EB[NK], RB[NK], Q2[NK], W2[NK];
#pragma unroll
    for (int k = 0; k < NK; k++) {
        const float mux = __ldg(p + k);
        const float muy = __ldg(p + NK + k);
        const float wk  = __ldg(p + 2 * NK + k);
        const float A   = __ldg(p + 3 * NK + 4 * k + 0);   // s00
        const float C   = __ldg(p + 3 * NK + 4 * k + 2);   // s10
        const float D   = __ldg(p + 3 * NK + 4 * k + 3);   // s11

        const float t   = x - mux;
        const float b0  = fmaf(t, A, -muy * C);
        const float b1  = -muy * D;
        const float al  = -h * fmaf(C, C, D * D);
        const float be  = -2.0f * h * fmaf(C, b0, D * b1);
        const float ga  = -h * fmaf(b0, b0, b1 * b1);

        EA[k] = pk2(fast_ex2(fmaf(fmaf(al, yA_lo, be), yA_lo, ga)),
                    fast_ex2(fmaf(fmaf(al, yA_hi, be), yA_hi, ga)));
        EB[k] = pk2(fast_ex2(fmaf(fmaf(al, yB_lo, be), yB_lo, ga)),
                    fast_ex2(fmaf(fmaf(al, yB_hi, be), yB_hi, ga)));

        const float ald = al * dl;
        const float a4  = 4.0f * ald;
        const float rc  = fmaf(a4, dl, 2.0f * be * dl);   // 4*al*dl^2 + 2*be*dl
        RA[k] = pk2(fast_ex2(fmaf(a4, yA_lo, rc)),
                    fast_ex2(fmaf(a4, yA_hi, rc)));
        RB[k] = pk2(fast_ex2(fmaf(a4, yB_lo, rc)),
                    fast_ex2(fmaf(a4, yB_hi, rc)));

        const float q = fast_ex2(8.0f * ald * dl);
        Q2[k] = pk2(q, q);
        W2[k] = pk2(wk, wk);
    }

    float* dst = out + (size_t)b * PIX + p0;

    float resA[4], resB[4];
#pragma unroll
    for (int s = 0; s < 4; s++) {
        // Tree accumulation, no carried register (depth 3)
        u64 gA = add2(add2(EA[0], EA[1]), add2(EA[2], EA[3]));
        u64 aA = add2(fma2(EA[1], W2[1], mul2(EA[0], W2[0])),
                      fma2(EA[3], W2[3], mul2(EA[2], W2[2])));
        u64 gB = add2(add2(EB[0], EB[1]), add2(EB[2], EB[3]));
        u64 aB = add2(fma2(EB[1], W2[1], mul2(EB[0], W2[0])),
                      fma2(EB[3], W2[3], mul2(EB[2], W2[2])));

        if (s < 3) {   // last-step advance is dead; skip explicitly
#pragma unroll
            for (int k = 0; k < NK; k++) {
                EA[k] = mul2(EA[k], RA[k]);  RA[k] = mul2(RA[k], Q2[k]);
                EB[k] = mul2(EB[k], RB[k]);  RB[k] = mul2(RB[k], Q2[k]);
            }
        }

        float glo, ghi, alo, ahi;
        upk2(gA, glo, ghi); upk2(aA, alo, ahi);
        resA[2 * (s & 1)]     = __saturatef(__fdividef(alo, fmaxf(glo, 1e-7f)));
        resA[2 * (s & 1) + 1] = __saturatef(__fdividef(ahi, fmaxf(ghi, 1e-7f)));
        upk2(gB, glo, ghi); upk2(aB, alo, ahi);
        resB[2 * (s & 1)]     = __saturatef(__fdividef(alo, fmaxf(glo, 1e-7f)));
        resB[2 * (s & 1) + 1] = __saturatef(__fdividef(ahi, fmaxf(ghi, 1e-7f)));

        if (s & 1) {   // two pairs ready per group -> aligned float4 stores
            const int v = (s >> 1);  // 0 or 1
            *reinterpret_cast<float4*>(dst + 4 * v) =
                make_float4(resA[0], resA[1], resA[2], resA[3]);
            *reinterpret_cast<float4*>(dst + 8 + 4 * v) =
                make_float4(resB[0], resB[1], resB[2], resB[3]);
        }
    }
}

extern "C" void kernel_launch(void* const* d_in, const int* in_sizes, int n_in,
                              void* d_out, int out_size) {
    const float* params = nullptr;
    for (int idx = 0; idx < n_in; idx++) {
        if (in_sizes[idx] == NBATCH * NPAR) params = (const float*)d_in[idx];
    }
    if (!params) params = (const float*)d_in[n_in - 1];

    float* out = (float*)d_out;
    dim3 grid(PIX / PPB, NBATCH);      // (16, 128) = 2048 blocks
    moe_gauss_kernel<<<grid, THREADS>>>(params, out);
}

// round 16
// speedup vs baseline: 1.1362x; 1.1362x over previous
#include <cuda_runtime.h>
#include <cuda_bf16.h>

// Problem constants (fixed by setup_inputs)
#define HEIGHT 256
#define WIDTH  256
#define NBATCH 128
#define NK     4
#define NPAR   28
#define PIX    (HEIGHT * WIDTH)
#define PPT    16                      // pixels per thread (8 packed pairs)
#define THREADS 256
#define PPB    (THREADS * PPT)         // 4096 pixels per block

typedef unsigned long long u64;

// ---- packed f32x2 helpers (sm_103a FFMA2 path, PTX-only) ----
__device__ __forceinline__ u64 pk2(float lo, float hi) {
    u64 r; asm("mov.b64 %0, {%1, %2};" : "=l"(r) : "f"(lo), "f"(hi)); return r;
}
__device__ __forceinline__ void upk2(u64 v, float& lo, float& hi) {
    asm("mov.b64 {%0, %1}, %2;" : "=f"(lo), "=f"(hi) : "l"(v));
}
__device__ __forceinline__ u64 fma2(u64 a, u64 b, u64 c) {
    u64 d; asm("fma.rn.f32x2 %0, %1, %2, %3;" : "=l"(d) : "l"(a), "l"(b), "l"(c)); return d;
}
__device__ __forceinline__ u64 mul2(u64 a, u64 b) {
    u64 d; asm("mul.rn.f32x2 %0, %1, %2;" : "=l"(d) : "l"(a), "l"(b)); return d;
}
__device__ __forceinline__ u64 add2(u64 a, u64 b) {
    u64 d; asm("add.rn.f32x2 %0, %1, %2;" : "=l"(d) : "l"(a), "l"(b)); return d;
}
__device__ __forceinline__ float fast_ex2(float x) {
    float r; asm("ex2.approx.f32 %0, %1;" : "=f"(r) : "f"(x)); return r;
}

__global__ __launch_bounds__(THREADS, 5)
void moe_gauss_kernel(const float* __restrict__ params, float* __restrict__ out) {
    const int b   = blockIdx.y;
    const int p0  = blockIdx.x * PPB + threadIdx.x * PPT;
    const int row = p0 >> 8;           // all 16 pixels share the same row (16 | 256)
    const int j0  = p0 & 255;

    const float* __restrict__ p = params + b * NPAR;

    const float inv255 = 1.0f / 255.0f;
    const float x = (float)row * inv255;
    const float h = 0.7213475204444817f;   // 0.5 * log2(e)

    // Quadratic-in-y expansion of the exponent, per Gaussian:
    //   ex2 argument = al*y^2 + be*y + ga   (-0.5*log2e folded into al,be,ga)
    u64 AL2[NK], BE2[NK], GA2[NK], W2[NK];
#pragma unroll
    for (int k = 0; k < NK; k++) {
        const float mux = __ldg(p + k);
        const float muy = __ldg(p + NK + k);
        const float wk  = __ldg(p + 2 * NK + k);
        const float A   = __ldg(p + 3 * NK + 4 * k + 0);   // s00
        const float C   = __ldg(p + 3 * NK + 4 * k + 2);   // s10
        const float D   = __ldg(p + 3 * NK + 4 * k + 3);   // s11

        const float t   = x - mux;
        const float b0  = fmaf(t, A, -muy * C);
        const float b1  = -muy * D;
        const float al  = -h * fmaf(C, C, D * D);
        const float be  = -2.0f * h * fmaf(C, b0, D * b1);
        const float ga  = -h * fmaf(b0, b0, b1 * b1);

        AL2[k] = pk2(al, al);
        BE2[k] = pk2(be, be);
        GA2[k] = pk2(ga, ga);
        W2[k]  = pk2(wk, wk);
    }

    const u64 DY2     = pk2(2.0f * inv255, 2.0f * inv255);
    const u64 NTWO2   = pk2(-2.0f, -2.0f);
    const u64 TWO2    = pk2(2.0f, 2.0f);
    u64 y2 = pk2((float)j0 * inv255, (float)(j0 + 1) * inv255);

    float* dst = out + (size_t)b * PIX + p0;

#pragma unroll
    for (int v = 0; v < PPT / 4; v++) {
        float4 r4;
        float* rp = &r4.x;
#pragma unroll
        for (int q = 0; q < 2; q++) {
            u64 g2 = 0ull;   // packed {0.0f, 0.0f}
            u64 a2 = 0ull;
#pragma unroll
            for (int k = 0; k < NK; k++) {
                const u64 s = fma2(y2, fma2(y2, AL2[k], BE2[k]), GA2[k]);
                float slo, shi;
                upk2(s, slo, shi);
                const u64 e2 = pk2(fast_ex2(slo), fast_ex2(shi));
                g2 = add2(g2, e2);
                a2 = fma2(e2, W2[k], a2);
            }
            // Packed Newton reciprocal of m = max(g, 1e-7): seed from integer
            // bit-hack (alu pipe), 2 iterations on the fma pipe. Replaces the
            // 2 MUFU RCPs per pair (MUFU is the binding pipe).
            float glo, ghi, alo, ahi;
            upk2(g2, glo, ghi);
            upk2(a2, alo, ahi);
            const float mlo = fmaxf(glo, 1e-7f);
            const float mhi = fmaxf(ghi, 1e-7f);
            const u64 m2 = pk2(mlo, mhi);
            const float r0lo = __int_as_float(0x7EF311C3 - __float_as_int(mlo));
            const float r0hi = __int_as_float(0x7EF311C3 - __float_as_int(mhi));
            u64 r2 = pk2(r0lo, r0hi);
            const u64 u2 = fma2(m2, r2, NTWO2);   // m*r0 - 2      (< 0)
            const u64 v2 = mul2(r2, u2);          // -r1
            const u64 w2 = fma2(m2, v2, TWO2);    // 2 - m*r1      (> 0)
            const u64 z2 = mul2(v2, w2);          // -r2
            float zlo, zhi;
            upk2(z2, zlo, zhi);
            rp[2 * q]     = __saturatef(alo * (-zlo));
            rp[2 * q + 1] = __saturatef(ahi * (-zhi));
            y2 = add2(y2, DY2);        // advance both columns by 2/255
        }
        // p0 is a multiple of 16 -> aligned float4 store, issued as ready
        *reinterpret_cast<float4*>(dst + 4 * v) = r4;
    }
}

extern "C" void kernel_launch(void* const* d_in, const int* in_sizes, int n_in,
                              void* d_out, int out_size) {
    const float* params = nullptr;
    for (int idx = 0; idx < n_in; idx++) {
        if (in_sizes[idx] == NBATCH * NPAR) params = (const float*)d_in[idx];
    }
    if (!params) params = (const float*)d_in[n_in - 1];

    float* out = (float*)d_out;
    dim3 grid(PIX / PPB, NBATCH);      // (16, 128) = 2048 blocks
    moe_gauss_kernel<<<grid, THREADS>>>(params, out);
}

// round 17
// speedup vs baseline: 1.1534x; 1.0152x over previous
#include <cuda_runtime.h>
#include <cuda_bf16.h>

// Problem constants (fixed by setup_inputs)
#define HEIGHT 256
#define WIDTH  256
#define NBATCH 128
#define NK     4
#define NPAR   28
#define PIX    (HEIGHT * WIDTH)
#define PPT    16                      // pixels per thread (8 packed pairs)
#define THREADS 256
#define PPB    (THREADS * PPT)         // 4096 pixels per block

typedef unsigned long long u64;

// ---- packed f32x2 helpers (sm_103a FFMA2 path, PTX-only) ----
__device__ __forceinline__ u64 pk2(float lo, float hi) {
    u64 r; asm("mov.b64 %0, {%1, %2};" : "=l"(r) : "f"(lo), "f"(hi)); return r;
}
__device__ __forceinline__ void upk2(u64 v, float& lo, float& hi) {
    asm("mov.b64 {%0, %1}, %2;" : "=f"(lo), "=f"(hi) : "l"(v));
}
__device__ __forceinline__ u64 fma2(u64 a, u64 b, u64 c) {
    u64 d; asm("fma.rn.f32x2 %0, %1, %2, %3;" : "=l"(d) : "l"(a), "l"(b), "l"(c)); return d;
}
__device__ __forceinline__ u64 mul2(u64 a, u64 b) {
    u64 d; asm("mul.rn.f32x2 %0, %1, %2;" : "=l"(d) : "l"(a), "l"(b)); return d;
}
__device__ __forceinline__ u64 add2(u64 a, u64 b) {
    u64 d; asm("add.rn.f32x2 %0, %1, %2;" : "=l"(d) : "l"(a), "l"(b)); return d;
}
__device__ __forceinline__ float fast_ex2(float x) {
    float r; asm("ex2.approx.f32 %0, %1;" : "=f"(r) : "f"(x)); return r;
}

__global__ __launch_bounds__(THREADS, 5)
void moe_gauss_kernel(const float* __restrict__ params, float* __restrict__ out) {
    const int b   = blockIdx.y;
    const int p0  = blockIdx.x * PPB + threadIdx.x * PPT;
    const int row = p0 >> 8;           // all 16 pixels share the same row (16 | 256)
    const int j0  = p0 & 255;

    const float* __restrict__ p = params + b * NPAR;

    const float inv255 = 1.0f / 255.0f;
    const float x = (float)row * inv255;
    const float h = 0.7213475204444817f;   // 0.5 * log2(e)

    // Quadratic-in-y expansion of the exponent, per Gaussian:
    //   ex2 argument = al*y^2 + be*y + ga   (-0.5*log2e folded into al,be,ga)
    u64 AL2[NK], BE2[NK], GA2[NK], W2[NK];
#pragma unroll
    for (int k = 0; k < NK; k++) {
        const float mux = __ldg(p + k);
        const float muy = __ldg(p + NK + k);
        const float wk  = __ldg(p + 2 * NK + k);
        const float A   = __ldg(p + 3 * NK + 4 * k + 0);   // s00
        const float C   = __ldg(p + 3 * NK + 4 * k + 2);   // s10
        const float D   = __ldg(p + 3 * NK + 4 * k + 3);   // s11

        const float t   = x - mux;
        const float b0  = fmaf(t, A, -muy * C);
        const float b1  = -muy * D;
        const float al  = -h * fmaf(C, C, D * D);
        const float be  = -2.0f * h * fmaf(C, b0, D * b1);
        const float ga  = -h * fmaf(b0, b0, b1 * b1);

        AL2[k] = pk2(al, al);
        BE2[k] = pk2(be, be);
        GA2[k] = pk2(ga, ga);
        W2[k]  = pk2(wk, wk);
    }

    const u64 DY2 = pk2(2.0f * inv255, 2.0f * inv255);
    u64 y2 = pk2((float)j0 * inv255, (float)(j0 + 1) * inv255);

    float* dst = out + (size_t)b * PIX + p0;

#pragma unroll
    for (int v = 0; v < PPT / 4; v++) {
        float4 r4;
        float* rp = &r4.x;
#pragma unroll
        for (int q = 0; q < 2; q++) {
            // 4 independent Horner + EX2 streams, then depth-2 tree reduction
            u64 e2[NK];
#pragma unroll
            for (int k = 0; k < NK; k++) {
                const u64 s = fma2(y2, fma2(y2, AL2[k], BE2[k]), GA2[k]);
                float slo, shi;
                upk2(s, slo, shi);
                e2[k] = pk2(fast_ex2(slo), fast_ex2(shi));
            }
            const u64 g2 = add2(add2(e2[0], e2[1]), add2(e2[2], e2[3]));
            const u64 a2 = add2(fma2(e2[1], W2[1], mul2(e2[0], W2[0])),
                                fma2(e2[3], W2[3], mul2(e2[2], W2[2])));

            float glo, ghi, alo, ahi;
            upk2(g2, glo, ghi);
            upk2(a2, alo, ahi);
            rp[2 * q]     = __saturatef(__fdividef(alo, fmaxf(glo, 1e-7f)));
            rp[2 * q + 1] = __saturatef(__fdividef(ahi, fmaxf(ghi, 1e-7f)));
            y2 = add2(y2, DY2);        // advance both columns by 2/255
        }
        // p0 is a multiple of 16 -> aligned float4 store, issued as ready
        *reinterpret_cast<float4*>(dst + 4 * v) = r4;
    }
}

extern "C" void kernel_launch(void* const* d_in, const int* in_sizes, int n_in,
                              void* d_out, int out_size) {
    const float* params = nullptr;
    for (int idx = 0; idx < n_in; idx++) {
        if (in_sizes[idx] == NBATCH * NPAR) params = (const float*)d_in[idx];
    }
    if (!params) params = (const float*)d_in[n_in - 1];

    float* out = (float*)d_out;
    dim3 grid(PIX / PPB, NBATCH);      // (16, 128) = 2048 blocks
    moe_gauss_kernel<<<grid, THREADS>>>(params, out);
}